// round 10
// baseline (speedup 1.0000x reference)
#include <cuda_runtime.h>
#include <stdint.h>

// Problem: emb_in [2048, 32] f32, sum_weights [2048] f32.
// Output [2048*2048, 65] f32, row k = i*2048 + j:
//   out[k][0:32]=emb[i], out[k][32:64]=emb[j], out[k][64]=w[j].
//
// R9: smem fill + one cp.async.bulk store per block -> 145.5us,
// DRAM 89.6%. Residual idle = CTA lifecycle bubbles (wait_group 0
// before exit, 37 waves of launch churn).
// R10: persistent CTAs, double-buffered smem, pipelined bulk_groups.
// A buffer is reused as soon as its TMA *smem reads* are done
// (wait_group.read 1); DRAM writes drain continuously behind.

#define N_ROWS     2048
#define ROW_LEN    65
#define R_CHUNK    64
#define CHUNK_F    (R_CHUNK * ROW_LEN)          // 4160 floats
#define CHUNK_B    (CHUNK_F * 4)                // 16,640 bytes (mult of 16)
#define N_CHUNKS   (N_ROWS * N_ROWS / R_CHUNK)  // 65536 chunks
#define GRID_CTAS  (148 * 6)                    // 888 persistent CTAs

__global__ __launch_bounds__(256)
void no_sparsity_persist_kernel(const float* __restrict__ emb,
                                const float* __restrict__ w,
                                float* __restrict__ out)
{
    __shared__ __align__(16) float s[2][CHUNK_F];   // 2 x 16,640 B

    const int tid  = threadIdx.x;
    const int lane = tid & 31;
    const int wr   = tid >> 5;                      // warp id, 0..7

    unsigned it = 0;
    for (unsigned c = blockIdx.x; c < N_CHUNKS; c += GRID_CTAS, ++it) {
        const unsigned b  = it & 1u;
        const unsigned k0 = c * (unsigned)R_CHUNK;  // first output row
        const unsigned i  = k0 >> 11;
        const unsigned j0 = k0 & 2047u;

        // Free buffer b: the group committed 2 iterations ago must have
        // finished READING smem. (No-op while <2 groups are committed.)
        if (tid == 0)
            asm volatile("cp.async.bulk.wait_group.read 1;" ::: "memory");
        __syncthreads();   // all threads see the buffer as free

        // ---- Fill smem image. Warp wr handles rows wr, wr+8, ... ----
        // Row stride 65 == 1 (mod 32): bank = (r + lane) % 32, conflict-free.
        const float a = __ldg(emb + i * 32u + lane);   // L1-resident bcast
        float* buf = s[b];
#pragma unroll
        for (int r = wr; r < R_CHUNK; r += 8) {
            const unsigned j = j0 + (unsigned)r;
            const float bb = __ldg(emb + j * 32u + lane);  // coalesced row
            float* srow = buf + r * ROW_LEN;
            srow[lane]      = a;                           // cols 0..31
            srow[32 + lane] = bb;                          // cols 32..63
            if (lane == 0) srow[64] = __ldg(w + j);        // col 64
        }
        __syncthreads();   // fills visible to the issuing thread

        if (tid == 0) {
            // Order generic-proxy STS before async-proxy TMA read.
            asm volatile("fence.proxy.async.shared::cta;" ::: "memory");
            const float* dst = out + (size_t)c * (size_t)CHUNK_F;
            uint32_t saddr = (uint32_t)__cvta_generic_to_shared(buf);
            asm volatile(
                "cp.async.bulk.global.shared::cta.bulk_group [%0], [%1], %2;"
                :: "l"(dst), "r"(saddr), "r"((unsigned)CHUNK_B)
                : "memory");
            asm volatile("cp.async.bulk.commit_group;" ::: "memory");
        }
    }

    // Final drain: all writes complete before kernel end.
    if (tid == 0)
        asm volatile("cp.async.bulk.wait_group 0;" ::: "memory");
}

extern "C" void kernel_launch(void* const* d_in, const int* in_sizes, int n_in,
                              void* d_out, int out_size)
{
    const float* emb = (const float*)d_in[0];   // [2048, 32] f32
    const float* w   = (const float*)d_in[1];   // [2048]     f32
    float* out       = (float*)d_out;

    no_sparsity_persist_kernel<<<GRID_CTAS, 256>>>(emb, w, out);
}

// round 11
// speedup vs baseline: 1.1682x; 1.1682x over previous
#include <cuda_runtime.h>
#include <stdint.h>

// Problem: emb_in [2048, 32] f32, sum_weights [2048] f32.
// Output [2048*2048, 65] f32, row k = i*2048 + j:
//   out[k][0:32]=emb[i], out[k][32:64]=emb[j], out[k][64]=w[j].
//
// R9 (best, 145.5us, DRAM 89.6%): smem fill + one cp.async.bulk store
// per 128-row block, full wait_group 0 before exit.
// R10 (persistent double-buffer) REGRESSED (170us): intra-CTA pipelining
// with block-wide syncs is worse than 6 independent CTAs/SM.
// R11 = R9 with ONE change: exit-wait is wait_group.read 0 (smem reads
// only). The DRAM write side keeps draining while the replacement CTA
// ramps — removes ~600-1000 idle cycles per CTA at each wave boundary.
// (CUTLASS TMA-store epilogue pattern; write visibility at kernel
// boundary is guaranteed by the kernel-end membar.)

#define N_ROWS     2048
#define ROW_LEN    65
#define R_CHUNK    128
#define CHUNK_F    (R_CHUNK * ROW_LEN)          // 8320 floats
#define CHUNK_B    (CHUNK_F * 4)                // 33,280 bytes (mult of 16)
#define N_CHUNKS   (N_ROWS * N_ROWS / R_CHUNK)  // 32768 blocks

__global__ __launch_bounds__(256)
void no_sparsity_tma_kernel(const float* __restrict__ emb,
                            const float* __restrict__ w,
                            float* __restrict__ out)
{
    __shared__ __align__(16) float s[CHUNK_F];

    const unsigned k0 = blockIdx.x * (unsigned)R_CHUNK;  // first output row
    const unsigned i  = k0 >> 11;                        // constant per block
    const unsigned j0 = k0 & 2047u;

    const int tid  = threadIdx.x;
    const int lane = tid & 31;
    const int wr   = tid >> 5;                           // warp id, 0..7

    // emb[i][lane]: one broadcast 128B line, L1-resident across the block.
    const float a = __ldg(emb + i * 32u + lane);

    // ---- Fill smem image. Warp wr handles rows wr, wr+8, ... (16 rows) ----
    // Row stride 65 == 1 (mod 32) -> bank = (r + lane) % 32, conflict-free.
#pragma unroll
    for (int r = wr; r < R_CHUNK; r += 8) {
        const unsigned j = j0 + (unsigned)r;
        const float b = __ldg(emb + j * 32u + lane);     // coalesced 128B row
        float* srow = s + r * ROW_LEN;
        srow[lane]      = a;                             // cols 0..31
        srow[32 + lane] = b;                             // cols 32..63
        if (lane == 0) srow[64] = __ldg(w + j);          // col 64
    }
    __syncthreads();

    // Order generic-proxy STS writes before the async-proxy TMA read.
    asm volatile("fence.proxy.async.shared::cta;" ::: "memory");

    // ---- Drain: one bulk TMA store, smem -> gmem ----
    if (tid == 0) {
        const float* dst = out + (size_t)blockIdx.x * (size_t)CHUNK_F;
        uint32_t saddr = (uint32_t)__cvta_generic_to_shared(s);
        asm volatile(
            "cp.async.bulk.global.shared::cta.bulk_group [%0], [%1], %2;"
            :: "l"(dst), "r"(saddr), "r"((unsigned)CHUNK_B)
            : "memory");
        asm volatile("cp.async.bulk.commit_group;" ::: "memory");
        // Wait only for the smem READS: that is all that must complete
        // before this CTA's smem can be retired. The gmem write side
        // drains while the next CTA ramps on this SM.
        asm volatile("cp.async.bulk.wait_group.read 0;" ::: "memory");
    }
}

extern "C" void kernel_launch(void* const* d_in, const int* in_sizes, int n_in,
                              void* d_out, int out_size)
{
    const float* emb = (const float*)d_in[0];   // [2048, 32] f32
    const float* w   = (const float*)d_in[1];   // [2048]     f32
    float* out       = (float*)d_out;

    no_sparsity_tma_kernel<<<N_CHUNKS, 256>>>(emb, w, out);
}